// round 7
// baseline (speedup 1.0000x reference)
#include <cuda_runtime.h>

namespace {
constexpr int N_COLS = 8192;
constexpr int W_MAX  = 15;     // widths w = 2..15
constexpr int NW     = 14;
constexpr int HALO   = 14;     // W_MAX - 1
constexpr int TPB    = 128;
constexpr int K_TOK  = 8;      // tokens per thread
constexpr int TILE   = TPB * K_TOK;        // 1024
constexpr float NEGV = -1.0e9f;
constexpr unsigned KEY_NINF = 0x007fffffu; // fkey(-inf)
}

// order-preserving float<->uint key (total order incl. -inf)
__device__ __forceinline__ unsigned fkey(float f) {
    int u = __float_as_int(f);
    return (u >= 0) ? ((unsigned)u | 0x80000000u) : ~(unsigned)u;
}
__device__ __forceinline__ float funkey(unsigned k) {
    unsigned u = (k & 0x80000000u) ? (k & 0x7fffffffu) : ~k;
    return __int_as_float((int)u);
}

__global__ __launch_bounds__(TPB, 5) void span_boost_kernel(
    const float* __restrict__ scores,
    const int*   __restrict__ mask,
    const float* __restrict__ gamma_p,
    const float* __restrict__ wlog,
    float*       __restrict__ out)
{
    __shared__ float    tailbuf[TPB][15];  // 14 used; stride 15 = conflict-free
    __shared__ unsigned xb[HALO];          // CTA-left-halo boost (keyed max)

    const float NINF = __int_as_float(0xff800000);
    const int   tid  = threadIdx.x;
    const int   row  = blockIdx.y;
    const int   col0 = blockIdx.x * TILE;
    const float* srow = scores + (size_t)row * N_COLS;
    const int*   mrow = mask   + (size_t)row * N_COLS;

    // ---- direct vector loads: tokens [tcol, tcol+24) (no smem staging) ----
    const int tcol = col0 + tid * K_TOK;
    float4 sv4[6]; int4 mv4[6];
    #pragma unroll
    for (int q = 0; q < 6; q++) {
        int g = tcol + 4 * q;
        if (g < N_COLS) {                  // aligned block fully in-row
            sv4[q] = *reinterpret_cast<const float4*>(srow + g);
            mv4[q] = *reinterpret_cast<const int4*>(mrow + g);
        } else {                           // past row end -> -inf sentinel
            sv4[q] = make_float4(NINF, NINF, NINF, NINF);
            mv4[q] = make_int4(1, 1, 1, 1);
        }
    }
    const float gamma = *gamma_p;

    // ---- per-thread softmax over 15 width logits (uniform loads) ----
    float ww[NW];
    {
        float lg[W_MAX];
        #pragma unroll
        for (int j = 0; j < W_MAX; j++) lg[j] = wlog[j];
        float mx = lg[0];
        #pragma unroll
        for (int j = 1; j < W_MAX; j++) mx = fmaxf(mx, lg[j]);
        float e[W_MAX], ssum = 0.f;
        #pragma unroll
        for (int j = 0; j < W_MAX; j++) { e[j] = __expf(lg[j] - mx); ssum += e[j]; }
        float inv = 1.f / ssum;
        #pragma unroll
        for (int j = 0; j < NW; j++) ww[j] = e[j + 1] * inv;   // widths 2..15
    }

    // ---- CTA-left halo: threads 0..13 handle start col0-14+tid ----
    if (tid < HALO) xb[tid] = KEY_NINF;
    if (tid < 32) __syncwarp();            // order init before atomics (warp 0)
    if (tid < HALO) {
        const int h0 = tid;
        float hv[W_MAX];                   // masked[col0-14+h0 .. col0+h0]
        #pragma unroll
        for (int k = 0; k < W_MAX; k++) {
            int g = col0 - HALO + h0 + k;
            hv[k] = (g >= 0) ? ((mrow[g] == 0) ? NEGV : srow[g]) : NINF;
        }
        float mm[NW];
        float m = fminf(hv[0], hv[1]);
        mm[0] = ww[0] * m;
        #pragma unroll
        for (int w = 3; w <= W_MAX; w++) {
            m = fminf(m, hv[w - 1]);
            mm[w - 2] = ww[w - 2] * m;
        }
        float g = mm[NW - 1];
        atomicMax(&xb[h0], fkey(g));       // d = 15 -> token h0
        #pragma unroll
        for (int d = W_MAX - 1; d >= 2; d--) {
            g = fmaxf(g, mm[d - 2]);
            int i = h0 + d - W_MAX;
            if (i >= 0) atomicMax(&xb[i], fkey(g));
        }
    }

    // ---- build masked r[0..21] in registers ----
    float r[22];
    #pragma unroll
    for (int q = 0; q < 5; q++) {
        const float* s = &sv4[q].x; const int* m = &mv4[q].x;
        #pragma unroll
        for (int k = 0; k < 4; k++)
            r[4*q+k] = (m[k] == 0) ? NEGV : s[k];
    }
    r[20] = (mv4[5].x == 0) ? NEGV : sv4[5].x;
    r[21] = (mv4[5].y == 0) ? NEGV : sv4[5].y;

    float boost[K_TOK + HALO];             // local tokens 0..21

    // ---- 8 starts, descending; incremental min; streamed retirement ----
    #pragma unroll
    for (int jj = 0; jj < K_TOK; jj++) {
        const int j = K_TOK - 1 - jj;      // 7 .. 0
        float h[NW];
        float m = fminf(r[j], r[j + 1]);
        h[0] = ww[0] * m;
        #pragma unroll
        for (int w = 3; w <= W_MAX; w++) {
            m = fminf(m, r[j + w - 1]);
            h[w - 2] = ww[w - 2] * m;
        }
        float g = h[NW - 1];                               // d = 15
        if (j == K_TOK - 1) boost[j + 14] = g;
        else                boost[j + 14] = fmaxf(boost[j + 14], g);
        #pragma unroll
        for (int d = W_MAX - 1; d >= 2; d--) {             // d = 14..2
            g = fmaxf(g, h[d - 2]);
            if (j == K_TOK - 1) boost[j + d - 1] = g;
            else                boost[j + d - 1] = fmaxf(boost[j + d - 1], g);
        }
        boost[j] = g;                                      // d = 1 (first touch)
        if (j >= 1) tailbuf[tid][j + 6] = boost[j + 14];   // retire token j+14
    }
    #pragma unroll
    for (int k = 0; k < 7; k++) tailbuf[tid][k] = boost[8 + k];

    __syncthreads();

    // ---- merge incoming contributions into own tokens 0..7 ----
    if (tid >= 2) {
        #pragma unroll
        for (int k = 0; k < K_TOK; k++)
            boost[k] = fmaxf(boost[k], tailbuf[tid - 1][k]);
        #pragma unroll
        for (int k = 0; k < 6; k++)
            boost[k] = fmaxf(boost[k], tailbuf[tid - 2][k + 8]);
    } else if (tid == 1) {
        #pragma unroll
        for (int k = 0; k < K_TOK; k++)
            boost[k] = fmaxf(boost[k], tailbuf[0][k]);
        #pragma unroll
        for (int k = 0; k < 6; k++)
            boost[k] = fmaxf(boost[k], funkey(xb[k + 8]));
    } else {
        #pragma unroll
        for (int k = 0; k < K_TOK; k++)
            boost[k] = fmaxf(boost[k], funkey(xb[k]));
    }

    // ---- epilogue: out = score + gamma * max(boost, masked) ----
    float* orow = out + (size_t)row * N_COLS;
    {
        float4 o;
        o.x = sv4[0].x + gamma * fmaxf(boost[0], r[0]);
        o.y = sv4[0].y + gamma * fmaxf(boost[1], r[1]);
        o.z = sv4[0].z + gamma * fmaxf(boost[2], r[2]);
        o.w = sv4[0].w + gamma * fmaxf(boost[3], r[3]);
        *reinterpret_cast<float4*>(&orow[tcol]) = o;
        o.x = sv4[1].x + gamma * fmaxf(boost[4], r[4]);
        o.y = sv4[1].y + gamma * fmaxf(boost[5], r[5]);
        o.z = sv4[1].z + gamma * fmaxf(boost[6], r[6]);
        o.w = sv4[1].w + gamma * fmaxf(boost[7], r[7]);
        *reinterpret_cast<float4*>(&orow[tcol + 4]) = o;
    }
}

extern "C" void kernel_launch(void* const* d_in, const int* in_sizes, int n_in,
                              void* d_out, int out_size)
{
    const float* scores = (const float*)d_in[0];
    const int*   mask   = (const int*)d_in[1];
    const float* gamma  = (const float*)d_in[2];
    const float* wlog   = (const float*)d_in[3];
    float* out = (float*)d_out;
    const int B = in_sizes[0] / N_COLS;   // 512
    dim3 grid(N_COLS / TILE, B);          // (8, 512)
    span_boost_kernel<<<grid, TPB>>>(scores, mask, gamma, wlog, out);
}

// round 8
// speedup vs baseline: 1.0762x; 1.0762x over previous
#include <cuda_runtime.h>

namespace {
constexpr int N_COLS = 8192;
constexpr int W_MAX  = 15;     // widths w = 2..15
constexpr int NW     = 14;
constexpr int HALO   = 14;     // W_MAX - 1
constexpr int TPB    = 128;    // 4 warps
constexpr int K_TOK  = 16;     // tokens per lane
constexpr int WTOK   = 32 * K_TOK;         // 512 tokens per warp
constexpr int TILE   = 4 * WTOK;           // 2048 tokens per CTA
constexpr float NEGV = -1.0e9f;
constexpr unsigned KEY_NINF = 0x007fffffu; // fkey(-inf)
}

// order-preserving float<->uint key (total order incl. -inf)
__device__ __forceinline__ unsigned fkey(float f) {
    int u = __float_as_int(f);
    return (u >= 0) ? ((unsigned)u | 0x80000000u) : ~(unsigned)u;
}
__device__ __forceinline__ float funkey(unsigned k) {
    unsigned u = (k & 0x80000000u) ? (k & 0x7fffffffu) : ~k;
    return __int_as_float((int)u);
}

__global__ __launch_bounds__(TPB, 6) void span_boost_kernel(
    const float* __restrict__ scores,
    const int*   __restrict__ mask,
    const float* __restrict__ gamma_p,
    const float* __restrict__ wlog,
    float*       __restrict__ out)
{
    __shared__ unsigned xb[4][16];         // per-warp left-halo boost (keyed)

    const float NINF = __int_as_float(0xff800000);
    const int tid  = threadIdx.x;
    const int lane = tid & 31;
    const int wid  = tid >> 5;
    const int row  = blockIdx.y;
    const float* srow = scores + (size_t)row * N_COLS;
    const int*   mrow = mask   + (size_t)row * N_COLS;

    const int wb = blockIdx.x * TILE + wid * WTOK;  // warp token base
    const int t0 = wb + lane * K_TOK;               // lane token base

    // ---- per-thread softmax over 15 width logits ----
    float ww[NW];
    {
        float lg[W_MAX];
        #pragma unroll
        for (int j = 0; j < W_MAX; j++) lg[j] = wlog[j];
        float mx = lg[0];
        #pragma unroll
        for (int j = 1; j < W_MAX; j++) mx = fmaxf(mx, lg[j]);
        float e[W_MAX], ssum = 0.f;
        #pragma unroll
        for (int j = 0; j < W_MAX; j++) { e[j] = __expf(lg[j] - mx); ssum += e[j]; }
        float inv = 1.f / ssum;
        #pragma unroll
        for (int j = 0; j < NW; j++) ww[j] = e[j + 1] * inv;   // widths 2..15
    }

    // ---- masked values r[0..29] for tokens t0..t0+29, direct LDG.128 ----
    float r[32];
    #pragma unroll
    for (int q = 0; q < 8; q++) {
        int g = t0 + 4 * q;                // 16B-aligned; fully in or out of row
        if (g < N_COLS) {
            float4 s4 = *reinterpret_cast<const float4*>(srow + g);
            int4   m4 = *reinterpret_cast<const int4*>(mrow + g);
            r[4*q+0] = (m4.x == 0) ? NEGV : s4.x;
            r[4*q+1] = (m4.y == 0) ? NEGV : s4.y;
            r[4*q+2] = (m4.z == 0) ? NEGV : s4.z;
            r[4*q+3] = (m4.w == 0) ? NEGV : s4.w;
        } else {
            r[4*q+0] = NINF; r[4*q+1] = NINF; r[4*q+2] = NINF; r[4*q+3] = NINF;
        }
    }

    // ---- init per-warp halo box ----
    if (lane < HALO) xb[wid][lane] = KEY_NINF;
    __syncwarp();

    float boost[K_TOK + HALO];             // local token slots 0..29

    // ---- 16 starts, descending; streamed shuffle handoff lane->lane+1 ----
    // Iter j: window-min chain, weighted suffix-max G, scatter to slots
    // j..j+14. Slot j+14 finalizes here -> shfl to lane+1, where it becomes
    // the FIRST TOUCH (assignment) of slot j-2. Lane 0 substitutes -inf and
    // gets its real left contributions from the halo box afterward.
    #pragma unroll
    for (int jj = 0; jj < K_TOK; jj++) {
        const int j = K_TOK - 1 - jj;      // 15 .. 0
        float h[NW];
        float m = fminf(r[j], r[j + 1]);
        h[0] = ww[0] * m;
        #pragma unroll
        for (int w = 3; w <= W_MAX; w++) {
            m = fminf(m, r[j + w - 1]);
            h[w - 2] = ww[w - 2] * m;
        }
        float g = h[NW - 1];                                // d = 15
        if (j == K_TOK - 1) boost[j + 14] = g;
        else                boost[j + 14] = fmaxf(boost[j + 14], g);
        #pragma unroll
        for (int d = W_MAX - 1; d >= 2; d--) {              // d = 14..2
            g = fmaxf(g, h[d - 2]);
            if (j == K_TOK - 1) boost[j + d - 1] = g;
            else                boost[j + d - 1] = fmaxf(boost[j + d - 1], g);
        }
        if (j >= K_TOK - 2) boost[j] = g;                   // d = 1: slots 14,15
        else                boost[j] = fmaxf(boost[j], g);  // incoming landed first
        if (j >= 2) {                                       // handoff slot j-2
            float tin = __shfl_up_sync(0xffffffffu, boost[j + 14], 1);
            boost[j - 2] = (lane == 0) ? NINF : tin;
        }
    }

    // ---- warp-left halo: lanes 0..13 compute start wb-14+lane ----
    if (lane < HALO) {
        const int h0 = lane;
        float hv[W_MAX];                   // masked[wb-14+h0 .. wb+h0]
        #pragma unroll
        for (int k = 0; k < W_MAX; k++) {
            int g = wb - HALO + h0 + k;
            hv[k] = (g >= 0) ? ((mrow[g] == 0) ? NEGV : srow[g]) : NINF;
        }
        float mm[NW];
        float m = fminf(hv[0], hv[1]);
        mm[0] = ww[0] * m;
        #pragma unroll
        for (int w = 3; w <= W_MAX; w++) {
            m = fminf(m, hv[w - 1]);
            mm[w - 2] = ww[w - 2] * m;
        }
        float g = mm[NW - 1];
        atomicMax(&xb[wid][h0], fkey(g));  // d = 15 -> warp token h0
        #pragma unroll
        for (int d = W_MAX - 1; d >= 2; d--) {
            g = fmaxf(g, mm[d - 2]);
            int i = h0 + d - W_MAX;
            if (i >= 0) atomicMax(&xb[wid][i], fkey(g));
        }
    }
    __syncwarp();
    if (lane == 0) {
        #pragma unroll
        for (int k = 0; k < HALO; k++)
            boost[k] = fmaxf(boost[k], funkey(xb[wid][k]));
    }

    // ---- epilogue: out = score + gamma * max(boost, masked) ----
    const float gamma = *gamma_p;
    float* orow = out + (size_t)row * N_COLS;
    #pragma unroll
    for (int q = 0; q < K_TOK / 4; q++) {
        float4 s4 = *reinterpret_cast<const float4*>(&srow[t0 + 4 * q]);
        float4 o;
        o.x = s4.x + gamma * fmaxf(boost[4*q+0], r[4*q+0]);
        o.y = s4.y + gamma * fmaxf(boost[4*q+1], r[4*q+1]);
        o.z = s4.z + gamma * fmaxf(boost[4*q+2], r[4*q+2]);
        o.w = s4.w + gamma * fmaxf(boost[4*q+3], r[4*q+3]);
        *reinterpret_cast<float4*>(&orow[t0 + 4 * q]) = o;
    }
}

extern "C" void kernel_launch(void* const* d_in, const int* in_sizes, int n_in,
                              void* d_out, int out_size)
{
    const float* scores = (const float*)d_in[0];
    const int*   mask   = (const int*)d_in[1];
    const float* gamma  = (const float*)d_in[2];
    const float* wlog   = (const float*)d_in[3];
    float* out = (float*)d_out;
    const int B = in_sizes[0] / N_COLS;   // 512
    dim3 grid(N_COLS / TILE, B);          // (4, 512)
    span_boost_kernel<<<grid, TPB>>>(scores, mask, gamma, wlog, out);
}